// round 8
// baseline (speedup 1.0000x reference)
#include <cuda_runtime.h>
#include <cuda_bf16.h>

// ConvSSM scan, spatial domain.
//   Phase 1: U_t = B (*) x_t for all (t,b,c)  — parallel, written in the
//            scan's per-thread register layout.
//   Phase 2: h_t = A (*) h_{t-1} + U_t        — 64 sequential steps, one CTA
//            per (b,c). h in registers (warp w: rows 4w..4w+3, lane l: cols
//            2l,2l+1). Horizontal wrap via u64 shfl; vertical halo via packed
//            double-buffered SMEM (1 STS.128/LDS.128); U prefetch distance 2.
// (*) = circular conv on the 64x64 torus (== reference zero-padded FFT product).

#define NT 64
#define NB 2
#define NC 32
#define NH 32
#define NW 32
#define NBC 64              // NB*NC chains
// U slice layout: slot(l,w) = l*9+w  (l=0..16 col pair, w=0..8 warp),
// each slot = 4 row-pairs (rows 4w..4w+3) = 8 floats contiguous.
#define USLOTS 153          // 17*9
#define USLICE (USLOTS * 8) // floats per (t,bc) slice = 1224

// 66 slices: +2 guard for unconditional distance-2 prefetch.
__device__ __align__(16) float g_U[(size_t)(NT + 2) * NBC * USLICE];

typedef unsigned long long u64;

__device__ __forceinline__ u64 pk(float lo, float hi) {
    u64 r; asm("mov.b64 %0, {%1, %2};" : "=l"(r) : "f"(lo), "f"(hi)); return r;
}
__device__ __forceinline__ float2 unpk(u64 v) {
    float2 f; asm("mov.b64 {%0, %1}, %2;" : "=f"(f.x), "=f"(f.y) : "l"(v)); return f;
}
__device__ __forceinline__ u64 f2fma(u64 a, u64 b, u64 c) {
    u64 d; asm("fma.rn.f32x2 %0, %1, %2, %3;" : "=l"(d) : "l"(a), "l"(b), "l"(c));
    return d;
}

// Operands for one input row from packed pair P (cols 2l,2l+1):
//   O0 = {x, x+1} = P ;  O2 = {x-2, x-1} = left-neighbor pair (u64 shfl) ;
//   O1 = {x-1, x}  (one pack).
__device__ __forceinline__ void mkops(u64 P, int src, u64& O0, u64& O1, u64& O2) {
    u64 L = __shfl_sync(0xffffffffu, P, src);
    float2 Pf = unpk(P), Lf = unpk(L);
    O0 = P; O2 = L; O1 = pk(Lf.y, Pf.x);
}
__device__ __forceinline__ u64 cdy(const u64* A2, int dy, u64 O0, u64 O1, u64 O2, u64 acc) {
    acc = f2fma(A2[3 * dy + 0], O0, acc);
    acc = f2fma(A2[3 * dy + 1], O1, acc);
    acc = f2fma(A2[3 * dy + 2], O2, acc);
    return acc;
}

// ---------------------------------------------------------------------------
// Phase 1: U = B (*) x (zero-padded x), one CTA per (t,b,c) slice.
// 192 threads; threads 0..152 each compute the 8 floats scan-thread (l,w)
// will read: rows 4w..4w+3 (rows >= 34 are zero), cols 2l,2l+1.
// ---------------------------------------------------------------------------
__global__ __launch_bounds__(192)
void u_precompute(const float* __restrict__ x, const float* __restrict__ Bk)
{
    __shared__ __align__(16) float xs[38 * 44];   // idx = actual + 2, zero border
    const int n   = blockIdx.x;           // n = t*NBC + bc
    const int c   = n & (NC - 1);
    const int tid = threadIdx.x;

    for (int i = tid; i < 38 * 44; i += 192) xs[i] = 0.0f;
    __syncthreads();

    const float2* xsl = (const float2*)(x + (size_t)n * (NH * NW));
    for (int i = tid; i < (NH * NW) / 2; i += 192) {
        const int r = i >> 4, c2 = (i & 15) * 2;
        float2 v = xsl[i];
        *(float2*)&xs[(r + 2) * 44 + c2 + 2] = v;
    }

    float Bw[9];
#pragma unroll
    for (int j = 0; j < 9; ++j) Bw[j] = Bk[c * 9 + j];
    __syncthreads();

    if (tid < USLOTS) {
        const int l = tid / 9;            // col pair 0..16 -> cols 2l,2l+1
        const int w = tid % 9;            // row group -> rows 4w..4w+3
        const int c0 = 2 * l;
        float o[4][2];
#pragma unroll
        for (int i = 0; i < 4; ++i) {
            const int r = 4 * w + i;      // rows 34,35 compute to 0 naturally
            o[i][0] = 0.f; o[i][1] = 0.f;
#pragma unroll
            for (int dy = 0; dy < 3; ++dy) {
                const float* rp = &xs[(r + 2 - dy) * 44 + c0 + 2];
#pragma unroll
                for (int dx = 0; dx < 3; ++dx) {
                    o[i][0] = fmaf(Bw[dy * 3 + dx], rp[-dx], o[i][0]);
                    o[i][1] = fmaf(Bw[dy * 3 + dx], rp[1 - dx], o[i][1]);
                }
            }
        }
        float* up = &g_U[(size_t)n * USLICE + tid * 8];
        *(float4*)(up)     = make_float4(o[0][0], o[0][1], o[1][0], o[1][1]);
        *(float4*)(up + 4) = make_float4(o[2][0], o[2][1], o[3][0], o[3][1]);
    }
}

// ---------------------------------------------------------------------------
// Phase 2: register-resident scan. 512 threads = 16 warps per CTA, 1 CTA/(b,c).
// ---------------------------------------------------------------------------
__global__ __launch_bounds__(512, 1)
void convssm_scan(const float* __restrict__ Ak, float* __restrict__ out)
{
    // halo[buf][w][lane] = {row 4w+2 pair, row 4w+3 pair} (16 B)
    __shared__ __align__(16) ulonglong2 halo[2][16][32];

    const int tid  = threadIdx.x;
    const int lane = tid & 31;
    const int w    = tid >> 5;
    const int bc   = blockIdx.x;
    const int c    = bc & (NC - 1);
    const int src  = (lane + 31) & 31;     // circular left neighbor
    const int row0 = 4 * w;

    u64 A2[9];
#pragma unroll
    for (int j = 0; j < 9; ++j) { float a = Ak[c * 9 + j]; A2[j] = pk(a, a); }

    // h_{-1} = 0 (packed state)
    u64 h0 = 0ull, h1 = 0ull, h2 = 0ull, h3 = 0ull;

    for (int i = tid; i < 2 * 16 * 32; i += 512)
        ((ulonglong2*)halo)[i] = make_ulonglong2(0ull, 0ull);

    // U stream (scan layout): slot (lane, w), 8 floats.
    const bool ul   = (lane < 17) && (w < 9);
    const float* up = g_U + (size_t)bc * USLICE + (lane * 9 + w) * 8;
    const size_t ustep = (size_t)NBC * USLICE;

    // Prefetch U_0, U_1 (distance-2 pipeline).
    u64 ub[2][4];
#pragma unroll
    for (int s = 0; s < 2; ++s) {
        float4 a = make_float4(0.f,0.f,0.f,0.f), b = a;
        if (ul) {
            a = *(const float4*)(up + (size_t)s * ustep);
            b = *(const float4*)(up + (size_t)s * ustep + 4);
        }
        ub[s][0] = pk(a.x, a.y); ub[s][1] = pk(a.z, a.w);
        ub[s][2] = pk(b.x, b.y); ub[s][3] = pk(b.z, b.w);
    }
    up += 2 * ustep;

    float* ob = out + (size_t)bc * (NH * NW) + row0 * NW + 2 * lane;
    const bool emits = (w < 8) && (lane < 16);
    const int rsl = (w + 15) & 15;         // warp above (circular): rows 4w-2,4w-1

    __syncthreads();

#pragma unroll 2
    for (int t = 0; t < NT; ++t) {
        const int pb = t & 1;              // halo read buffer / U slot parity

        // Vertical halo rows (h_{t-1} rows 4w-2, 4w-1), one LDS.128.
        ulonglong2 hv = halo[pb][rsl][lane];

        // acc = U_t
        u64 acc0 = ub[pb][0], acc1 = ub[pb][1], acc2 = ub[pb][2], acc3 = ub[pb][3];

        // Prefetch U_{t+2} into the vacated slot (no consumer this step).
        float4 na = make_float4(0.f,0.f,0.f,0.f), nb = na;
        if (ul) {
            na = *(const float4*)(up);
            nb = *(const float4*)(up + 4);
        }
        up += ustep;

        // acc += A (*) h_{t-1}
        u64 O0, O1, O2;
        mkops(hv.x, src, O0, O1, O2);   // input row -2
        acc0 = cdy(A2, 2, O0, O1, O2, acc0);
        mkops(hv.y, src, O0, O1, O2);   // input row -1
        acc0 = cdy(A2, 1, O0, O1, O2, acc0);
        acc1 = cdy(A2, 2, O0, O1, O2, acc1);
        mkops(h0, src, O0, O1, O2);     // input row 0
        acc0 = cdy(A2, 0, O0, O1, O2, acc0);
        acc1 = cdy(A2, 1, O0, O1, O2, acc1);
        acc2 = cdy(A2, 2, O0, O1, O2, acc2);
        mkops(h1, src, O0, O1, O2);     // input row 1
        acc1 = cdy(A2, 0, O0, O1, O2, acc1);
        acc2 = cdy(A2, 1, O0, O1, O2, acc2);
        acc3 = cdy(A2, 2, O0, O1, O2, acc3);
        mkops(h2, src, O0, O1, O2);     // input row 2
        acc2 = cdy(A2, 0, O0, O1, O2, acc2);
        acc3 = cdy(A2, 1, O0, O1, O2, acc3);
        mkops(h3, src, O0, O1, O2);     // input row 3
        acc3 = cdy(A2, 0, O0, O1, O2, acc3);

        h0 = acc0; h1 = acc1; h2 = acc2; h3 = acc3;

        // Publish bottom-2 rows for the warp below (one STS.128).
        halo[pb ^ 1][w][lane] = make_ulonglong2(acc2, acc3);

        // Emit cropped 32x32 output.
        if (emits) {
            float* o = ob + (size_t)t * (NBC * NH * NW);
            *(u64*)(o)          = acc0;
            *(u64*)(o + NW)     = acc1;
            *(u64*)(o + 2 * NW) = acc2;
            *(u64*)(o + 3 * NW) = acc3;
        }

        // Commit U_{t+2} into slot pb (consumed at step t+2).
        ub[pb][0] = pk(na.x, na.y); ub[pb][1] = pk(na.z, na.w);
        ub[pb][2] = pk(nb.x, nb.y); ub[pb][3] = pk(nb.z, nb.w);

        __syncthreads();
    }
}

extern "C" void kernel_launch(void* const* d_in, const int* in_sizes, int n_in,
                              void* d_out, int out_size) {
    const float* x  = (const float*)d_in[0];
    const float* Ak = (const float*)d_in[1];
    const float* Bk = (const float*)d_in[2];
    float* out = (float*)d_out;
    u_precompute<<<NT * NBC, 192>>>(x, Bk);
    convssm_scan<<<NBC, 512>>>(Ak, out);
}

// round 9
// speedup vs baseline: 1.0752x; 1.0752x over previous
#include <cuda_runtime.h>
#include <cuda_bf16.h>

// ConvSSM scan, spatial domain.
//   Phase 1: U_t = B (*) x_t for all (t,b,c), parallel, stored in the scan's
//            per-thread layout (81 slots x 16 floats per slice).
//   Phase 2: h_t = A (*) h_{t-1} + U_t. One 256-thread CTA per (b,c) chain,
//            thread owns a 4x4 pixel tile in registers (packed f32x2 pairs).
//            Horizontal wrap via one u64 shfl per input row; vertical halo via
//            double-buffered SMEM read with a direct 6-column window.
// (*) = circular conv on the 64x64 torus (== reference zero-padded FFT product).

#define NT 64
#define NB 2
#define NC 32
#define NH 32
#define NW 32
#define NBC 64
#define USLOT 81              // 9x9 (g,l) slots cover support rows/cols < 36
#define USLICE (USLOT * 16)   // floats per (t,bc) slice

// +1 guard slice for unconditional distance-1 prefetch.
__device__ __align__(16) float g_U[(size_t)(NT + 1) * NBC * USLICE];

typedef unsigned long long u64;

__device__ __forceinline__ u64 pk(float lo, float hi) {
    u64 r; asm("mov.b64 %0, {%1, %2};" : "=l"(r) : "f"(lo), "f"(hi)); return r;
}
__device__ __forceinline__ float2 unpk(u64 v) {
    float2 f; asm("mov.b64 {%0, %1}, %2;" : "=f"(f.x), "=f"(f.y) : "l"(v)); return f;
}
__device__ __forceinline__ u64 f2fma(u64 a, u64 b, u64 c) {
    u64 d; asm("fma.rn.f32x2 %0, %1, %2, %3;" : "=l"(d) : "l"(a), "l"(b), "l"(c));
    return d;
}

// One input row (pairs P0={c,c+1}, P1={c+2,c+3}, LP={c-2,c-1}) contributing
// with vertical tap dy to the two output pairs (aA, aB).
__device__ __forceinline__ void crow(const u64* A2, int dy,
                                     u64 P0, u64 P1, u64 M0, u64 M1, u64 LP,
                                     u64& aA, u64& aB) {
    aA = f2fma(A2[3 * dy + 0], P0, aA);
    aA = f2fma(A2[3 * dy + 1], M0, aA);
    aA = f2fma(A2[3 * dy + 2], LP, aA);
    aB = f2fma(A2[3 * dy + 0], P1, aB);
    aB = f2fma(A2[3 * dy + 1], M1, aB);
    aB = f2fma(A2[3 * dy + 2], P0, aB);
}
// Build the two misaligned middle pairs for a row.
__device__ __forceinline__ void mkrow(u64 P0, u64 P1, u64 LP, u64& M0, u64& M1) {
    float2 p0 = unpk(P0), p1 = unpk(P1), lp = unpk(LP);
    M0 = pk(lp.y, p0.x);
    M1 = pk(p0.y, p1.x);
}

// ---------------------------------------------------------------------------
// Phase 1: U = B (*) x (zero-padded x). One CTA per (t,b,c) slice, 128 thr.
// Threads 0..80: slot (g=tid/9, l=tid%9) = rows 4g..4g+3, cols 4l..4l+3.
// ---------------------------------------------------------------------------
__global__ __launch_bounds__(128)
void u_precompute(const float* __restrict__ x, const float* __restrict__ Bk)
{
    __shared__ __align__(16) float xs[38 * 44];   // idx = actual + 2, zero border
    const int n   = blockIdx.x;                   // n = t*NBC + bc
    const int c   = n & (NC - 1);
    const int tid = threadIdx.x;

    for (int i = tid; i < 38 * 44; i += 128) xs[i] = 0.0f;
    __syncthreads();

    const float2* xsl = (const float2*)(x + (size_t)n * (NH * NW));
    for (int i = tid; i < (NH * NW) / 2; i += 128) {
        const int r = i >> 4, c2 = (i & 15) * 2;
        float2 v = xsl[i];
        *(float2*)&xs[(r + 2) * 44 + c2 + 2] = v;
    }

    float Bw[9];
#pragma unroll
    for (int j = 0; j < 9; ++j) Bw[j] = Bk[c * 9 + j];
    __syncthreads();

    if (tid < USLOT) {
        const int g  = tid / 9;
        const int l  = tid % 9;
        const int c0 = 4 * l;
        float* up = &g_U[(size_t)n * USLICE + tid * 16];
#pragma unroll
        for (int i = 0; i < 4; ++i) {
            const int r = 4 * g + i;      // rows >= 34 compute to 0 naturally
            float o[4] = {0.f, 0.f, 0.f, 0.f};
#pragma unroll
            for (int dy = 0; dy < 3; ++dy) {
                const float* rp = &xs[(r + 2 - dy) * 44 + c0 + 2];
#pragma unroll
                for (int j = 0; j < 4; ++j)
#pragma unroll
                    for (int dx = 0; dx < 3; ++dx)
                        o[j] = fmaf(Bw[dy * 3 + dx], rp[j - dx], o[j]);
            }
            *(float4*)(up + i * 4) = make_float4(o[0], o[1], o[2], o[3]);
        }
    }
}

// ---------------------------------------------------------------------------
// Phase 2: register-resident scan. 256 threads = 8 warps per CTA, 1 CTA/(b,c).
// ---------------------------------------------------------------------------
__global__ __launch_bounds__(256, 1)
void convssm_scan(const float* __restrict__ Ak, float* __restrict__ out)
{
    // halo[buf][g][j][64]: rows 4g+2+j published by group g; read windowed.
    __shared__ __align__(16) float halo[2][16][2][64];

    const int tid  = threadIdx.x;
    const int lane = tid & 31;
    const int g    = tid >> 4;            // row group: rows 4g..4g+3
    const int l    = tid & 15;            // col group: cols 4l..4l+3
    const int c0   = 4 * l;
    const int bc   = blockIdx.x;
    const int c    = bc & (NC - 1);
    const int src  = (lane & 16) | ((lane + 15) & 15);  // circular left in half
    const int gm1  = (g + 15) & 15;
    const int cwl  = (c0 + 62) & 63;      // wrapped col index of {c0-2,c0-1}

    u64 A2[9];
#pragma unroll
    for (int j = 0; j < 9; ++j) { float a = Ak[c * 9 + j]; A2[j] = pk(a, a); }

    // State h_{-1} = 0: hA[i]={c0,c0+1}, hB[i]={c0+2,c0+3} for row 4g+i.
    u64 hA[4] = {0,0,0,0}, hB[4] = {0,0,0,0};

    for (int i = tid; i < 2 * 16 * 2 * 64; i += 256) (&halo[0][0][0][0])[i] = 0.f;

    // U stream.
    const bool ul = (g < 9) && (l < 9);
    const float* up = g_U + (size_t)bc * USLICE + (g * 9 + l) * 16;
    const size_t ust = (size_t)NBC * USLICE;

    float4 u0 = make_float4(0,0,0,0), u1 = u0, u2 = u0, u3 = u0;
    if (ul) {
        u0 = *(const float4*)(up);      u1 = *(const float4*)(up + 4);
        u2 = *(const float4*)(up + 8);  u3 = *(const float4*)(up + 12);
    }
    up += ust;

    float* ob = out + (size_t)bc * (NH * NW) + (4 * g) * NW + c0;
    const bool emits = (g < 8) && (l < 8);

    __syncthreads();

    for (int t = 0; t < NT; ++t) {
        const int pb = t & 1;

        // Vertical halo rows (h_{t-1} rows 4g-2, 4g-1): direct windowed LDS.
        const float* h0p = halo[pb][gm1][0];
        const float* h1p = halo[pb][gm1][1];
        u64    Lm2 = *(const u64*)(h0p + cwl);
        float4 Hm2 = *(const float4*)(h0p + c0);
        u64    Lm1 = *(const u64*)(h1p + cwl);
        float4 Hm1 = *(const float4*)(h1p + c0);

        // acc = U_t
        u64 aA0 = pk(u0.x,u0.y), aB0 = pk(u0.z,u0.w);
        u64 aA1 = pk(u1.x,u1.y), aB1 = pk(u1.z,u1.w);
        u64 aA2 = pk(u2.x,u2.y), aB2 = pk(u2.z,u2.w);
        u64 aA3 = pk(u3.x,u3.y), aB3 = pk(u3.z,u3.w);

        // Prefetch U_{t+1} (guard slice at t = NT-1).
        float4 n0 = make_float4(0,0,0,0), n1 = n0, n2 = n0, n3 = n0;
        if (ul) {
            n0 = *(const float4*)(up);      n1 = *(const float4*)(up + 4);
            n2 = *(const float4*)(up + 8);  n3 = *(const float4*)(up + 12);
        }
        up += ust;

        // acc += A (*) h_{t-1}
        u64 P0, P1, LP, M0, M1;
        // input row -2 -> out row 0 (dy=2)
        P0 = pk(Hm2.x, Hm2.y); P1 = pk(Hm2.z, Hm2.w); LP = Lm2;
        mkrow(P0, P1, LP, M0, M1);
        crow(A2, 2, P0, P1, M0, M1, LP, aA0, aB0);
        // input row -1 -> out rows 0 (dy=1), 1 (dy=2)
        P0 = pk(Hm1.x, Hm1.y); P1 = pk(Hm1.z, Hm1.w); LP = Lm1;
        mkrow(P0, P1, LP, M0, M1);
        crow(A2, 1, P0, P1, M0, M1, LP, aA0, aB0);
        crow(A2, 2, P0, P1, M0, M1, LP, aA1, aB1);
        // input row 0 -> out rows 0,1,2
        P0 = hA[0]; P1 = hB[0]; LP = __shfl_sync(0xffffffffu, hB[0], src);
        mkrow(P0, P1, LP, M0, M1);
        crow(A2, 0, P0, P1, M0, M1, LP, aA0, aB0);
        crow(A2, 1, P0, P1, M0, M1, LP, aA1, aB1);
        crow(A2, 2, P0, P1, M0, M1, LP, aA2, aB2);
        // input row 1 -> out rows 1,2,3
        P0 = hA[1]; P1 = hB[1]; LP = __shfl_sync(0xffffffffu, hB[1], src);
        mkrow(P0, P1, LP, M0, M1);
        crow(A2, 0, P0, P1, M0, M1, LP, aA1, aB1);
        crow(A2, 1, P0, P1, M0, M1, LP, aA2, aB2);
        crow(A2, 2, P0, P1, M0, M1, LP, aA3, aB3);
        // input row 2 -> out rows 2,3
        P0 = hA[2]; P1 = hB[2]; LP = __shfl_sync(0xffffffffu, hB[2], src);
        mkrow(P0, P1, LP, M0, M1);
        crow(A2, 0, P0, P1, M0, M1, LP, aA2, aB2);
        crow(A2, 1, P0, P1, M0, M1, LP, aA3, aB3);
        // input row 3 -> out row 3
        P0 = hA[3]; P1 = hB[3]; LP = __shfl_sync(0xffffffffu, hB[3], src);
        mkrow(P0, P1, LP, M0, M1);
        crow(A2, 0, P0, P1, M0, M1, LP, aA3, aB3);

        hA[0] = aA0; hB[0] = aB0; hA[1] = aA1; hB[1] = aB1;
        hA[2] = aA2; hB[2] = aB2; hA[3] = aA3; hB[3] = aB3;

        // Publish rows 4g+2, 4g+3 for the group below (2 STS.128).
        {
            float2 a = unpk(aA2), b = unpk(aB2);
            *(float4*)&halo[pb ^ 1][g][0][c0] = make_float4(a.x, a.y, b.x, b.y);
            float2 e = unpk(aA3), f = unpk(aB3);
            *(float4*)&halo[pb ^ 1][g][1][c0] = make_float4(e.x, e.y, f.x, f.y);
        }

        // Emit cropped 32x32 output (4 STG.128).
        if (emits) {
            float* o = ob + (size_t)t * (NBC * NH * NW);
            float2 a, b;
            a = unpk(aA0); b = unpk(aB0);
            *(float4*)(o)          = make_float4(a.x, a.y, b.x, b.y);
            a = unpk(aA1); b = unpk(aB1);
            *(float4*)(o + NW)     = make_float4(a.x, a.y, b.x, b.y);
            a = unpk(aA2); b = unpk(aB2);
            *(float4*)(o + 2 * NW) = make_float4(a.x, a.y, b.x, b.y);
            a = unpk(aA3); b = unpk(aB3);
            *(float4*)(o + 3 * NW) = make_float4(a.x, a.y, b.x, b.y);
        }

        u0 = n0; u1 = n1; u2 = n2; u3 = n3;

        __syncthreads();
    }
}

extern "C" void kernel_launch(void* const* d_in, const int* in_sizes, int n_in,
                              void* d_out, int out_size) {
    const float* x  = (const float*)d_in[0];
    const float* Ak = (const float*)d_in[1];
    const float* Bk = (const float*)d_in[2];
    float* out = (float*)d_out;
    u_precompute<<<NT * NBC, 128>>>(x, Bk);
    convssm_scan<<<NBC, 256>>>(Ak, out);
}